// round 1
// baseline (speedup 1.0000x reference)
#include <cuda_runtime.h>
#include <math.h>

#define BB_  64
#define NC_  20
#define KK_  150
#define CC_  2048
#define TLEN_ 750
#define INV_T (1.0f/0.07f)
#define EPSF 1e-7f

// ---------------- device scratch (no allocations allowed) ----------------
__device__ float g_q1[BB_*CC_], g_q2[BB_*CC_];
__device__ float g_q1n2[BB_], g_q2n2[BB_];
__device__ float g_dotA[BB_*KK_], g_dotB[BB_*KK_];
__device__ float g_nrmA[BB_*KK_], g_nrmB[BB_*KK_];
__device__ float g_lposA[BB_], g_lposB[BB_], g_msqA[BB_], g_msqB[BB_];
__device__ float g_ncep[BB_];
__device__ float g_acc[8];
#define ACC_CLS 0
#define ACC_REL 1
#define ACC_ACTW 2
#define ACC_ACTTH 3

// ---------------- reduction helper: result valid in ALL threads ----------------
__device__ __forceinline__ float bRed(float v, float* sbuf, bool ismax) {
#pragma unroll
    for (int o = 16; o; o >>= 1) {
        float t = __shfl_xor_sync(0xffffffffu, v, o);
        v = ismax ? fmaxf(v, t) : (v + t);
    }
    if ((threadIdx.x & 31) == 0) sbuf[threadIdx.x >> 5] = v;
    __syncthreads();
    int nw = (blockDim.x + 31) >> 5;
    float r = ismax ? -1e30f : 0.f;
    for (int i = 0; i < nw; i++) r = ismax ? fmaxf(r, sbuf[i]) : (r + sbuf[i]);
    __syncthreads();
    return r;
}

// ---------------- K1: column sums of HA/HB + ||sum||^2 ----------------
// grid 128 = 2 tensors x 64 batch; block 256, each thread owns 8 cols (strided float4)
__global__ __launch_bounds__(256) void k1_hsum(const float* __restrict__ HA,
                                               const float* __restrict__ HB) {
    int bx = blockIdx.x;
    if (bx == 0 && threadIdx.x < 8) g_acc[threadIdx.x] = 0.f;  // zero accumulators (used by K4/K5)
    int tensor = bx >> 6, b = bx & 63;
    const float4* base = (const float4*)((tensor ? HB : HA) + (size_t)b * KK_ * CC_);
    float* qdst = (tensor ? g_q2 : g_q1) + b * CC_;
    int tid = threadIdx.x;
    float4 a0 = {0,0,0,0}, a1 = {0,0,0,0};
#pragma unroll 5
    for (int k = 0; k < KK_; k++) {
        const float4* row = base + k * (CC_ / 4);
        float4 v0 = row[tid], v1 = row[tid + 256];
        a0.x += v0.x; a0.y += v0.y; a0.z += v0.z; a0.w += v0.w;
        a1.x += v1.x; a1.y += v1.y; a1.z += v1.z; a1.w += v1.w;
    }
    ((float4*)qdst)[tid]       = a0;
    ((float4*)qdst)[tid + 256] = a1;
    float s = a0.x*a0.x + a0.y*a0.y + a0.z*a0.z + a0.w*a0.w
            + a1.x*a1.x + a1.y*a1.y + a1.z*a1.z + a1.w*a1.w;
    __shared__ float sbuf[8];
    s = bRed(s, sbuf, false);
    if (tid == 0) (tensor ? g_q2n2 : g_q1n2)[b] = s;
}

// ---------------- K2: stream EA/EB once: row dots vs partner q, row norms,
//                  in-block column sums -> l_pos dot with self q and ||Esum||^2 ----------------
__global__ __launch_bounds__(256) void k2_epass(const float* __restrict__ EA,
                                                const float* __restrict__ EB) {
    int bx = blockIdx.x;
    int tensor = bx >> 6, b = bx & 63;   // tensor 0: EA (partner q2), 1: EB (partner q1)
    const float4* base  = (const float4*)((tensor ? EB : EA) + (size_t)b * KK_ * CC_);
    const float4* qpart = (const float4*)((tensor ? g_q1 : g_q2) + b * CC_);
    const float4* qself = (const float4*)((tensor ? g_q2 : g_q1) + b * CC_);
    float* dotdst = (tensor ? g_dotB : g_dotA) + b * KK_;
    float* nrmdst = (tensor ? g_nrmB : g_nrmA) + b * KK_;

    int tid = threadIdx.x, w = tid >> 5, l = tid & 31;
    __shared__ float wdot[8][KK_];
    __shared__ float wsq[8][KK_];
    __shared__ float sbuf[8];

    float4 q0 = qpart[tid], q1 = qpart[tid + 256];
    float4 c0 = {0,0,0,0}, c1 = {0,0,0,0};
#pragma unroll 5
    for (int k = 0; k < KK_; k++) {
        const float4* row = base + k * (CC_ / 4);
        float4 v0 = row[tid], v1 = row[tid + 256];
        c0.x += v0.x; c0.y += v0.y; c0.z += v0.z; c0.w += v0.w;
        c1.x += v1.x; c1.y += v1.y; c1.z += v1.z; c1.w += v1.w;
        float dp = v0.x*q0.x + v0.y*q0.y + v0.z*q0.z + v0.w*q0.w
                 + v1.x*q1.x + v1.y*q1.y + v1.z*q1.z + v1.w*q1.w;
        float sp = v0.x*v0.x + v0.y*v0.y + v0.z*v0.z + v0.w*v0.w
                 + v1.x*v1.x + v1.y*v1.y + v1.z*v1.z + v1.w*v1.w;
#pragma unroll
        for (int o = 16; o; o >>= 1) {
            dp += __shfl_down_sync(0xffffffffu, dp, o);
            sp += __shfl_down_sync(0xffffffffu, sp, o);
        }
        if (l == 0) { wdot[w][k] = dp; wsq[w][k] = sp; }
    }
    __syncthreads();
    for (int k = tid; k < KK_; k += 256) {
        float d = 0.f, s = 0.f;
#pragma unroll
        for (int ww = 0; ww < 8; ww++) { d += wdot[ww][k]; s += wsq[ww][k]; }
        dotdst[k] = d;
        nrmdst[k] = s;
    }
    // l_pos dot (q_self . Esum) and ||Esum||^2, computed from in-register column sums
    float4 s0 = qself[tid], s1 = qself[tid + 256];
    float lp = c0.x*s0.x + c0.y*s0.y + c0.z*s0.z + c0.w*s0.w
             + c1.x*s1.x + c1.y*s1.y + c1.z*s1.z + c1.w*s1.w;
    float ms = c0.x*c0.x + c0.y*c0.y + c0.z*c0.z + c0.w*c0.w
             + c1.x*c1.x + c1.y*c1.y + c1.z*c1.z + c1.w*c1.w;
    float lpr = bRed(lp, sbuf, false);
    if (tid == 0) (tensor ? g_lposB : g_lposA)[b] = lpr;
    float msr = bRed(ms, sbuf, false);
    if (tid == 0) (tensor ? g_msqB : g_msqA)[b] = msr;
}

// ---------------- K3: per-b logits + logsumexp for both NCE terms ----------------
__global__ __launch_bounds__(192) void k3_nce(const float* __restrict__ att) {
    int b = blockIdx.x, tid = threadIdx.x;
    __shared__ float sl[2][KK_ + 1];
    __shared__ float sbuf[8];
    float rq1 = rsqrtf(g_q1n2[b]), rq2 = rsqrtf(g_q2n2[b]);
    for (int i = tid; i <= KK_; i += blockDim.x) {
        float v1, v2;
        if (i == 0) {
            v1 = g_lposA[b] * rq1 * rsqrtf(g_msqA[b]);
            v2 = g_lposB[b] * rq2 * rsqrtf(g_msqB[b]);
        } else {
            int k = i - 1;
            v1 = att[b*300 + k]       * g_dotB[b*KK_ + k] * rq1 * rsqrtf(g_nrmB[b*KK_ + k]);
            v2 = att[b*300 + 150 + k] * g_dotA[b*KK_ + k] * rq2 * rsqrtf(g_nrmA[b*KK_ + k]);
        }
        sl[0][i] = v1 * INV_T;
        sl[1][i] = v2 * INV_T;
    }
    __syncthreads();
    float m1 = -1e30f, m2 = -1e30f;
    for (int i = tid; i <= KK_; i += blockDim.x) {
        m1 = fmaxf(m1, sl[0][i]); m2 = fmaxf(m2, sl[1][i]);
    }
    m1 = bRed(m1, sbuf, true);
    m2 = bRed(m2, sbuf, true);
    float s1 = 0.f, s2 = 0.f;
    for (int i = tid; i <= KK_; i += blockDim.x) {
        s1 += expf(sl[0][i] - m1); s2 += expf(sl[1][i] - m2);
    }
    s1 = bRed(s1, sbuf, false);
    s2 = bRed(s2, sbuf, false);
    if (tid == 0) {
        float lse1 = m1 + logf(s1), lse2 = m2 + logf(s2);
        g_ncep[b] = (lse1 - sl[0][0]) + (lse2 - sl[1][0]);
    }
}

// ---------------- K4: cls + rel + act (small terms) ----------------
// blocks 0..93:   loss_act windows (8 t per block) + theta term
// blocks 94..125: loss_rel grid-stride
// block  126:     loss_cls
__global__ __launch_bounds__(256) void k4_small(const float* __restrict__ vs,
                                                const float* __restrict__ label,
                                                const float* __restrict__ res,
                                                const float* __restrict__ red,
                                                const float* __restrict__ a0,
                                                const float* __restrict__ a2) {
    int bx = blockIdx.x, tid = threadIdx.x;
    __shared__ float sbuf[8];
    if (bx < 94) {
        int t0 = bx * 8;
        __shared__ float s0[64][19];
        __shared__ float s2s[64][19];
        for (int i = tid; i < 64 * 18; i += 256) {
            int b = i / 18, col = i % 18;
            int g = t0 - 6 + col;
            g = min(max(g, 0), TLEN_ - 1);
            s0[b][col]  = a0[b * TLEN_ + g];
            s2s[b][col] = a2[b * TLEN_ + g];
        }
        __syncthreads();
        int w = tid >> 5, l = tid & 31;
        int tl = w;                 // warp w handles t_local = w (8 warps)
        int t = t0 + tl;
        float accw = 0.f;
        if (t < TLEN_) {
            int tc = tl + 6;        // center column in tile
            for (int j = 0; j < 11; j++) {
                int g = t0 - 6 + tl + j;
                int gc = min(max(g, 0), TLEN_ - 1);
                int col = gc - (t0 - 6);
                float sq = 0.f, asum = 0.f;
#pragma unroll
                for (int h = 0; h < 2; h++) {
                    int b = l + 32 * h;
                    float d0 = s0[b][tc] - s0[b][col];
                    sq += d0 * d0;
                    asum += fabsf(s2s[b][tc] - s2s[b][col]);
                }
#pragma unroll
                for (int o = 16; o; o >>= 1) {
                    sq   += __shfl_down_sync(0xffffffffu, sq, o);
                    asum += __shfl_down_sync(0xffffffffu, asum, o);
                }
                if (l == 0) accw += expf(-0.5f * sq) * (asum * (1.f / 64.f));
            }
        }
        if (l == 0) atomicAdd(&g_acc[ACC_ACTW], accw);
        // theta term for this t-chunk
        float th = 0.f;
        for (int i = tid; i < 64 * 8; i += 256) {
            int b = i >> 3, tl2 = i & 7;
            if (t0 + tl2 < TLEN_) {
                float d = s0[b][tl2 + 6] - s2s[b][tl2 + 6];
                th += d * d;
            }
        }
        th = bRed(th, sbuf, false);
        if (tid == 0) atomicAdd(&g_acc[ACC_ACTTH], th);
    } else if (bx < 94 + 32) {
        float s = 0.f;
        for (int i = (bx - 94) * 256 + tid; i < 2 * BB_ * TLEN_; i += 32 * 256) {
            float a = res[i], d = red[i];
            s += (1.f - a) * (1.f - a) + d * d;
        }
        s = bRed(s, sbuf, false);
        if (tid == 0) atomicAdd(&g_acc[ACC_REL], s);
    } else {
        __shared__ float rs[64];
        for (int i = tid; i < 64; i += 256) {
            float s = 0.f;
            for (int j = 0; j < NC_; j++) s += label[i * NC_ + j];
            rs[i] = s;
        }
        __syncthreads();
        float s = 0.f;
        for (int i = tid; i < BB_ * NC_; i += 256) {
            int b = i / NC_;
            float lab = label[i] / rs[b];
            float v = fminf(fmaxf(vs[i], EPSF), 1.f - EPSF);
            s += lab * logf(v) + (1.f - lab) * log1pf(-v);
        }
        s = bRed(s, sbuf, false);
        if (tid == 0) atomicAdd(&g_acc[ACC_CLS], s);
    }
}

// ---------------- K5: compose final 5 outputs ----------------
__global__ void k5_final(float* __restrict__ out) {
    int tid = threadIdx.x;  // 64 threads
    float s = g_ncep[tid];
#pragma unroll
    for (int o = 16; o; o >>= 1) s += __shfl_down_sync(0xffffffffu, s, o);
    __shared__ float sb[2];
    if ((tid & 31) == 0) sb[tid >> 5] = s;
    __syncthreads();
    if (tid == 0) {
        float snico = (sb[0] + sb[1]) * (1.f / 64.f);
        float cls = -g_acc[ACC_CLS] * (1.f / (BB_ * NC_));
        float rel = g_acc[ACC_REL] * (1.f / (2.f * BB_ * TLEN_));
        float act = g_acc[ACC_ACTW] + 0.1f * g_acc[ACC_ACTTH] * (1.f / 64.f);  // E_THETA=0.1, E_ALPHA=1
        float total = cls + 0.01f * snico + act + 0.1f * rel;                   // THETA=0.1
        out[0] = total; out[1] = cls; out[2] = snico; out[3] = act; out[4] = rel;
    }
}

extern "C" void kernel_launch(void* const* d_in, const int* in_sizes, int n_in,
                              void* d_out, int out_size) {
    const float* vs    = (const float*)d_in[0];
    const float* label = (const float*)d_in[1];
    const float* HA    = (const float*)d_in[2];
    const float* EA    = (const float*)d_in[3];
    const float* HB    = (const float*)d_in[4];
    const float* EB    = (const float*)d_in[5];
    const float* res   = (const float*)d_in[6];
    const float* red   = (const float*)d_in[7];
    const float* a0    = (const float*)d_in[8];
    const float* a2    = (const float*)d_in[9];
    const float* att   = (const float*)d_in[10];
    (void)in_sizes; (void)n_in; (void)out_size;

    k1_hsum<<<128, 256>>>(HA, HB);
    k2_epass<<<128, 256>>>(EA, EB);
    k3_nce<<<64, 192>>>(att);
    k4_small<<<127, 256>>>(vs, label, res, red, a0, a2);
    k5_final<<<1, 64>>>((float*)d_out);
}

// round 3
// speedup vs baseline: 1.4220x; 1.4220x over previous
#include <cuda_runtime.h>
#include <math.h>

#define BB_  64
#define NC_  20
#define KK_  150
#define CC_  2048
#define TLEN_ 750
#define INV_T (1.0f/0.07f)
#define EPSF 1e-7f
#define NCHUNK 4
#define CH_F4 128          // float4s per chunk (512 floats)
#define B_F4 512           // float4s per (b) row of q/esum

// ---------------- device scratch ----------------
__device__ float g_q1[BB_*CC_], g_q2[BB_*CC_];
__device__ float g_es1[BB_*CC_], g_es2[BB_*CC_];
__device__ float g_qn2p[2*BB_*NCHUNK];
__device__ float g_dotp[2*NCHUNK*BB_*KK_];
__device__ float g_nrmp[2*NCHUNK*BB_*KK_];
__device__ float g_ncep[BB_];
__device__ float g_acc[8];
#define ACC_CLS 0
#define ACC_REL 1
#define ACC_ACTW 2
#define ACC_ACTTH 3

__device__ __forceinline__ float bRed(float v, float* sbuf, bool ismax) {
#pragma unroll
    for (int o = 16; o; o >>= 1) {
        float t = __shfl_xor_sync(0xffffffffu, v, o);
        v = ismax ? fmaxf(v, t) : (v + t);
    }
    if ((threadIdx.x & 31) == 0) sbuf[threadIdx.x >> 5] = v;
    __syncthreads();
    int nw = (blockDim.x + 31) >> 5;
    float r = ismax ? -1e30f : 0.f;
    for (int i = 0; i < nw; i++) r = ismax ? fmaxf(r, sbuf[i]) : (r + sbuf[i]);
    __syncthreads();
    return r;
}

// ---------------- K1: column sums of HA/HB + ||sum||^2 partials ----------------
// grid 512 = 2 tensors x 64 b x 4 c-chunks; 128 threads; thread owns 1 float4 col group
__global__ __launch_bounds__(128) void k1_hsum(const float* __restrict__ HA,
                                               const float* __restrict__ HB) {
    int bx = blockIdx.x, tid = threadIdx.x;
    if (bx == 0 && tid < 8) g_acc[tid] = 0.f;
    int tensor = bx >> 8, b = (bx >> 2) & 63, chunk = bx & 3;
    const float4* p = (const float4*)((tensor ? HB : HA) + (size_t)b * KK_ * CC_)
                      + chunk * CH_F4 + tid;
    float4 a = {0,0,0,0};
#pragma unroll 10
    for (int k = 0; k < KK_; k++) {
        float4 v = p[k * (CC_/4)];
        a.x += v.x; a.y += v.y; a.z += v.z; a.w += v.w;
    }
    float* q = (tensor ? g_q2 : g_q1) + b * CC_;
    ((float4*)q)[chunk * CH_F4 + tid] = a;
    float s = a.x*a.x + a.y*a.y + a.z*a.z + a.w*a.w;
#pragma unroll
    for (int o = 16; o; o >>= 1) s += __shfl_down_sync(0xffffffffu, s, o);
    __shared__ float sb[4];
    if ((tid & 31) == 0) sb[tid >> 5] = s;
    __syncthreads();
    if (tid == 0)
        g_qn2p[(tensor*BB_ + b)*NCHUNK + chunk] = sb[0] + sb[1] + sb[2] + sb[3];
}

// ---------------- K2: stream EA/EB once ----------------
// per block (tensor,b,chunk): column sums -> g_es*, per-row dot vs partner q +
// per-row sq-norm -> per-chunk partials (3-shfl to 4 lanes, combine at end)
__global__ __launch_bounds__(128) void k2_epass(const float* __restrict__ EA,
                                                const float* __restrict__ EB) {
    int bx = blockIdx.x, tid = threadIdx.x;
    int tensor = bx >> 8, b = (bx >> 2) & 63, chunk = bx & 3;
    int w = tid >> 5, l = tid & 31;
    const float4* p = (const float4*)((tensor ? EB : EA) + (size_t)b * KK_ * CC_)
                      + chunk * CH_F4 + tid;
    const float4* qp = (const float4*)(tensor ? g_q1 : g_q2) + b * B_F4 + chunk * CH_F4 + tid;

    __shared__ float wdot[4][KK_][4];
    __shared__ float wsq[4][KK_][4];

    float4 q = *qp;
    float4 c = {0,0,0,0};
#pragma unroll 10
    for (int k = 0; k < KK_; k++) {
        float4 v = p[k * (CC_/4)];
        c.x += v.x; c.y += v.y; c.z += v.z; c.w += v.w;
        float dp = v.x*q.x + v.y*q.y + v.z*q.z + v.w*q.w;
        float sp = v.x*v.x + v.y*v.y + v.z*v.z + v.w*v.w;
        dp += __shfl_down_sync(0xffffffffu, dp, 16);
        sp += __shfl_down_sync(0xffffffffu, sp, 16);
        dp += __shfl_down_sync(0xffffffffu, dp, 8);
        sp += __shfl_down_sync(0xffffffffu, sp, 8);
        dp += __shfl_down_sync(0xffffffffu, dp, 4);
        sp += __shfl_down_sync(0xffffffffu, sp, 4);
        if (l < 4) { wdot[w][k][l] = dp; wsq[w][k][l] = sp; }
    }
    float* es = (tensor ? g_es2 : g_es1);
    ((float4*)es)[b * B_F4 + chunk * CH_F4 + tid] = c;
    __syncthreads();
    int slot = ((tensor*NCHUNK + chunk)*BB_ + b)*KK_;
    for (int k = tid; k < KK_; k += 128) {
        float d = 0.f, s = 0.f;
#pragma unroll
        for (int ww = 0; ww < 4; ww++)
#pragma unroll
            for (int ll = 0; ll < 4; ll++) { d += wdot[ww][k][ll]; s += wsq[ww][k][ll]; }
        g_dotp[slot + k] = d;
        g_nrmp[slot + k] = s;
    }
}

// ---------------- K4 merged: nce-finalize | act | rel | cls ----------------
// blocks [0,64): per-b NCE logits+logsumexp (incl. l_pos/msq from g_es)
// blocks [64,158): loss_act windows; [158,222): loss_rel; 222: loss_cls
__global__ __launch_bounds__(256) void k4_small(const float* __restrict__ vs,
                                                const float* __restrict__ label,
                                                const float* __restrict__ res,
                                                const float* __restrict__ red,
                                                const float* __restrict__ a0,
                                                const float* __restrict__ a2,
                                                const float* __restrict__ att) {
    int bx = blockIdx.x, tid = threadIdx.x;
    __shared__ float sbuf[8];
    if (bx < 64) {
        int b = bx;
        __shared__ float sl[2][KK_ + 1];
        const float4* q1p = (const float4*)g_q1 + b * B_F4;
        const float4* q2p = (const float4*)g_q2 + b * B_F4;
        const float4* e1p = (const float4*)g_es1 + b * B_F4;
        const float4* e2p = (const float4*)g_es2 + b * B_F4;
        float lpA = 0.f, msA = 0.f, lpB = 0.f, msB = 0.f;
        for (int i = tid; i < B_F4; i += 256) {
            float4 e = e1p[i], q = q1p[i];
            lpA += e.x*q.x + e.y*q.y + e.z*q.z + e.w*q.w;
            msA += e.x*e.x + e.y*e.y + e.z*e.z + e.w*e.w;
            e = e2p[i]; q = q2p[i];
            lpB += e.x*q.x + e.y*q.y + e.z*q.z + e.w*q.w;
            msB += e.x*e.x + e.y*e.y + e.z*e.z + e.w*e.w;
        }
        lpA = bRed(lpA, sbuf, false); msA = bRed(msA, sbuf, false);
        lpB = bRed(lpB, sbuf, false); msB = bRed(msB, sbuf, false);
        const float* n1 = g_qn2p + (0*BB_ + b)*NCHUNK;
        const float* n2 = g_qn2p + (1*BB_ + b)*NCHUNK;
        float rq1 = rsqrtf(n1[0]+n1[1]+n1[2]+n1[3]);
        float rq2 = rsqrtf(n2[0]+n2[1]+n2[2]+n2[3]);
        for (int i = tid; i <= KK_; i += 256) {
            float v1, v2;
            if (i == 0) {
                v1 = lpA * rq1 * rsqrtf(msA);
                v2 = lpB * rq2 * rsqrtf(msB);
            } else {
                int k = i - 1;
                float dA = 0.f, nA = 0.f, dB = 0.f, nB = 0.f;
#pragma unroll
                for (int c = 0; c < NCHUNK; c++) {
                    int sA = ((0*NCHUNK + c)*BB_ + b)*KK_ + k;
                    int sB = ((1*NCHUNK + c)*BB_ + b)*KK_ + k;
                    dA += g_dotp[sA]; nA += g_nrmp[sA];
                    dB += g_dotp[sB]; nB += g_nrmp[sB];
                }
                v1 = att[b*300 + k]       * dB * rq1 * rsqrtf(nB);
                v2 = att[b*300 + 150 + k] * dA * rq2 * rsqrtf(nA);
            }
            sl[0][i] = v1 * INV_T;
            sl[1][i] = v2 * INV_T;
        }
        __syncthreads();
        float m1 = -1e30f, m2 = -1e30f;
        for (int i = tid; i <= KK_; i += 256) {
            m1 = fmaxf(m1, sl[0][i]); m2 = fmaxf(m2, sl[1][i]);
        }
        m1 = bRed(m1, sbuf, true);
        m2 = bRed(m2, sbuf, true);
        float s1 = 0.f, s2 = 0.f;
        for (int i = tid; i <= KK_; i += 256) {
            s1 += expf(sl[0][i] - m1); s2 += expf(sl[1][i] - m2);
        }
        s1 = bRed(s1, sbuf, false);
        s2 = bRed(s2, sbuf, false);
        if (tid == 0) {
            float lse1 = m1 + logf(s1), lse2 = m2 + logf(s2);
            g_ncep[b] = (lse1 - sl[0][0]) + (lse2 - sl[1][0]);
        }
    } else if (bx < 158) {
        int t0 = (bx - 64) * 8;
        __shared__ float s0[64][19];
        __shared__ float s2s[64][19];
        for (int i = tid; i < 64 * 18; i += 256) {
            int b = i / 18, col = i % 18;
            int g = t0 - 6 + col;
            g = min(max(g, 0), TLEN_ - 1);
            s0[b][col]  = a0[b * TLEN_ + g];
            s2s[b][col] = a2[b * TLEN_ + g];
        }
        __syncthreads();
        int w = tid >> 5, l = tid & 31;
        int t = t0 + w;
        float accw = 0.f;
        if (t < TLEN_) {
            int tc = w + 6;
            for (int j = 0; j < 11; j++) {
                int g = t0 - 6 + w + j;
                int gc = min(max(g, 0), TLEN_ - 1);
                int col = gc - (t0 - 6);
                float sq = 0.f, asum = 0.f;
#pragma unroll
                for (int h = 0; h < 2; h++) {
                    int b = l + 32 * h;
                    float d0 = s0[b][tc] - s0[b][col];
                    sq += d0 * d0;
                    asum += fabsf(s2s[b][tc] - s2s[b][col]);
                }
#pragma unroll
                for (int o = 16; o; o >>= 1) {
                    sq   += __shfl_down_sync(0xffffffffu, sq, o);
                    asum += __shfl_down_sync(0xffffffffu, asum, o);
                }
                if (l == 0) accw += expf(-0.5f * sq) * (asum * (1.f / 64.f));
            }
        }
        if (l == 0) atomicAdd(&g_acc[ACC_ACTW], accw);
        float th = 0.f;
        for (int i = tid; i < 64 * 8; i += 256) {
            int b = i >> 3, tl2 = i & 7;
            if (t0 + tl2 < TLEN_) {
                float d = s0[b][tl2 + 6] - s2s[b][tl2 + 6];
                th += d * d;
            }
        }
        th = bRed(th, sbuf, false);
        if (tid == 0) atomicAdd(&g_acc[ACC_ACTTH], th);
    } else if (bx < 222) {
        const float4* rs4 = (const float4*)res;
        const float4* rd4 = (const float4*)red;
        float s = 0.f;
        int n4 = 2 * BB_ * TLEN_ / 4;   // 24000
        for (int i = (bx - 158) * 256 + tid; i < n4; i += 64 * 256) {
            float4 a = rs4[i], d = rd4[i];
            s += (1.f-a.x)*(1.f-a.x) + (1.f-a.y)*(1.f-a.y)
               + (1.f-a.z)*(1.f-a.z) + (1.f-a.w)*(1.f-a.w)
               + d.x*d.x + d.y*d.y + d.z*d.z + d.w*d.w;
        }
        s = bRed(s, sbuf, false);
        if (tid == 0) atomicAdd(&g_acc[ACC_REL], s);
    } else {
        __shared__ float rs[64];
        for (int i = tid; i < 64; i += 256) {
            float s = 0.f;
            for (int j = 0; j < NC_; j++) s += label[i * NC_ + j];
            rs[i] = s;
        }
        __syncthreads();
        float s = 0.f;
        for (int i = tid; i < BB_ * NC_; i += 256) {
            int b = i / NC_;
            float lab = label[i] / rs[b];
            float v = fminf(fmaxf(vs[i], EPSF), 1.f - EPSF);
            s += lab * logf(v) + (1.f - lab) * log1pf(-v);
        }
        s = bRed(s, sbuf, false);
        if (tid == 0) atomicAdd(&g_acc[ACC_CLS], s);
    }
}

// ---------------- K5: compose final 5 outputs ----------------
__global__ void k5_final(float* __restrict__ out) {
    int tid = threadIdx.x;  // 64 threads
    float s = g_ncep[tid];
#pragma unroll
    for (int o = 16; o; o >>= 1) s += __shfl_down_sync(0xffffffffu, s, o);
    __shared__ float sb[2];
    if ((tid & 31) == 0) sb[tid >> 5] = s;
    __syncthreads();
    if (tid == 0) {
        float snico = (sb[0] + sb[1]) * (1.f / 64.f);
        float cls = -g_acc[ACC_CLS] * (1.f / (BB_ * NC_));
        float rel = g_acc[ACC_REL] * (1.f / (2.f * BB_ * TLEN_));
        float act = g_acc[ACC_ACTW] + 0.1f * g_acc[ACC_ACTTH] * (1.f / 64.f);
        float total = cls + 0.01f * snico + act + 0.1f * rel;
        out[0] = total; out[1] = cls; out[2] = snico; out[3] = act; out[4] = rel;
    }
}

extern "C" void kernel_launch(void* const* d_in, const int* in_sizes, int n_in,
                              void* d_out, int out_size) {
    const float* vs    = (const float*)d_in[0];
    const float* label = (const float*)d_in[1];
    const float* HA    = (const float*)d_in[2];
    const float* EA    = (const float*)d_in[3];
    const float* HB    = (const float*)d_in[4];
    const float* EB    = (const float*)d_in[5];
    const float* res   = (const float*)d_in[6];
    const float* red   = (const float*)d_in[7];
    const float* a0    = (const float*)d_in[8];
    const float* a2    = (const float*)d_in[9];
    const float* att   = (const float*)d_in[10];
    (void)in_sizes; (void)n_in; (void)out_size;

    k1_hsum<<<512, 128>>>(HA, HB);
    k2_epass<<<512, 128>>>(EA, EB);
    k4_small<<<223, 256>>>(vs, label, res, red, a0, a2, att);
    k5_final<<<1, 64>>>((float*)d_out);
}